// round 13
// baseline (speedup 1.0000x reference)
#include <cuda_runtime.h>
#include <math.h>
#include <limits.h>

#define BB 8
#define HH 256
#define WW 256
#define KK 100
#define JJ 17
#define HW (HH*WW)
#define NCH (BB + BB*JJ)      // 144 topk blocks
#define NSTREAM 304
#define MAXC 12288
#define MSEL 512
#define WMAX 6144
#define TPB 512
#define TCNT 4                 // sample crossing target
#define THRESH_F 0.1f
#define NEGBIG (-1e30f)

// ---------------- scratch (device globals) ----------------
__device__ float g_top_scores[BB][KK];
__device__ int   g_top_inds[BB][KK];
__device__ float g_bboxes[BB][KK][4];
__device__ int   g_ready[BB];
__device__ int   g_ticket;

__device__ __forceinline__ float sigf(float x) { return 1.0f / (1.0f + expf(-x)); }
__device__ __forceinline__ unsigned fkey(float v) {
    unsigned b = __float_as_uint(v);
    return b ^ ((b & 0x80000000u) ? 0xFFFFFFFFu : 0x80000000u);
}

__global__ void reset_kernel() {
    if (threadIdx.x == 0) g_ticket = 0;
    if (threadIdx.x < BB) g_ready[threadIdx.x] = 0;
}

// ---------------- mega kernel ----------------
__global__ void __launch_bounds__(TPB, 2)
mega_kernel(const float* __restrict__ hm, const float* __restrict__ wh,
            const float* __restrict__ hps, const float* __restrict__ reg,
            const float* __restrict__ hmhp, const float* __restrict__ hpo,
            float* __restrict__ out,
            long e1, long e2, long e3, long e4, long e5, long e6, long o6) {
    extern __shared__ char smem_raw[];
    unsigned* ckeys = (unsigned*)smem_raw;                       // MAXC sigmoid bits
    unsigned short* cinds = (unsigned short*)(ckeys + MAXC);     // MAXC pixel idx

    const int tid = threadIdx.x;

    if (blockIdx.x >= NCH) {
        // ============ streaming: ticketed 128KB chunks (8192 float4 = 16/thread), MLP-8 ============
        __shared__ int s_chunk;
        const int CH4 = 8192;   // float4 per chunk; divides every segment boundary exactly
        int nsc = (int)(e6 / CH4);
        float4* out4 = (float4*)out;
        while (true) {
            __syncthreads();
            if (tid == 0) s_chunk = atomicAdd(&g_ticket, 1);
            __syncthreads();
            int c = s_chunk;
            if (c >= nsc) return;
            long base = (long)c * CH4;
            const float4* src; bool sg = false;
            if (base < e1)      { src = (const float4*)hm   + base;        sg = true; }
            else if (base < e2) { src = (const float4*)wh   + (base - e1); }
            else if (base < e3) { src = (const float4*)hps  + (base - e2); }
            else if (base < e4) { src = (const float4*)reg  + (base - e3); }
            else if (base < e5) { src = (const float4*)hmhp + (base - e4); sg = true; }
            else                { src = (const float4*)hpo  + (base - e5); }
            #pragma unroll
            for (int h = 0; h < 2; h++) {
                float4 v[8];
                #pragma unroll
                for (int u = 0; u < 8; u++) v[u] = src[tid + (h * 8 + u) * TPB];
                if (sg) {
                    #pragma unroll
                    for (int u = 0; u < 8; u++) {
                        v[u].x = sigf(v[u].x); v[u].y = sigf(v[u].y);
                        v[u].z = sigf(v[u].z); v[u].w = sigf(v[u].w);
                    }
                }
                #pragma unroll
                for (int u = 0; u < 8; u++) out4[base + tid + (h * 8 + u) * TPB] = v[u];
            }
        }
    }

    // ============ topk block ============
    __shared__ int s_count;
    __shared__ int hist[8][256];
    __shared__ int wtot[8];
    __shared__ unsigned s_selk[MSEL];
    __shared__ int s_seli[MSEL];
    __shared__ int s_m;
    __shared__ int s_bin, s_nh;
    __shared__ int s_nw;
    __shared__ unsigned short s_work[WMAX];
    __shared__ float shx[KK], shy[KK], shs[KK];

    const int ch = blockIdx.x;
    const int lane = tid & 31;
    const bool is_writer = (ch < BB);
    const int e = ch - BB;
    const int b = is_writer ? ch : (e / JJ);
    const int j = is_writer ? 0 : (e % JJ);

    const float* src = is_writer ? (hm + (long)ch * HW)
                                 : (hmhp + (long)e * HW);
    const float4* src4 = (const float4*)src;

    // ---- Phase 0: sampled threshold (top-byte histogram of 512 strided pixels) ----
    if (tid == 0) s_bin = 0;
    for (int h = tid; h < 256; h += TPB) hist[0][h] = 0;
    __syncthreads();
    {
        unsigned sk = fkey(src[tid * 128]);
        atomicAdd(&hist[0][sk >> 24], 1);
    }
    __syncthreads();
    int cbin0 = 0;
    if (tid < 256) {
        cbin0 = hist[0][tid];
        int suf = cbin0;
        #pragma unroll
        for (int off = 1; off < 32; off <<= 1) {
            int v = __shfl_down_sync(0xffffffffu, suf, off);
            if (lane + off < 32) suf += v;
        }
        int wid = tid >> 5;
        if (lane == 0) wtot[wid] = suf;
        __syncwarp();
        hist[1][tid] = suf - cbin0;
    }
    __syncthreads();
    if (tid < 256) {
        int wid = tid >> 5;
        int hsum = 0;
        #pragma unroll
        for (int w = 0; w < 8; w++) if (w > wid) hsum += wtot[w];
        int sexcl = hist[1][tid] + hsum;
        if (sexcl < TCNT && sexcl + cbin0 >= TCNT) s_bin = tid;
    }
    __syncthreads();
    float T;
    {
        unsigned tk = (unsigned)s_bin << 24;
        T = (tk & 0x80000000u) ? __uint_as_float(tk & 0x7FFFFFFFu) : __uint_as_float(~tk);
    }
    __syncthreads();

    // ---- Phase 1: pass A (MLP-8 scan -> worklist) + pass B (NMS on worklist) ----
    int count;
    while (true) {
        if (tid == 0) { s_nw = 0; s_count = 0; }
        __syncthreads();

        if (T != NEGBIG) {
            // pass A: batched unconditional loads, per-quad max, aggregate push
            #pragma unroll
            for (int ib = 0; ib < 4; ib++) {
                float4 v[8]; float cm[8];
                #pragma unroll
                for (int u = 0; u < 8; u++) v[u] = src4[tid + (ib * 8 + u) * TPB];
                #pragma unroll
                for (int u = 0; u < 8; u++)
                    cm[u] = fmaxf(fmaxf(v[u].x, v[u].y), fmaxf(v[u].z, v[u].w));
                #pragma unroll
                for (int u = 0; u < 8; u++) {
                    bool hit = cm[u] >= T;
                    unsigned ball = __ballot_sync(0xffffffffu, hit);
                    if (ball) {
                        int leader = __ffs(ball) - 1;
                        int basep = 0;
                        if (lane == leader) basep = atomicAdd(&s_nw, __popc(ball));
                        basep = __shfl_sync(0xffffffffu, basep, leader);
                        if (hit) {
                            int pos = basep + __popc(ball & ((1u << lane) - 1u));
                            if (pos < WMAX) s_work[pos] = (unsigned short)(tid + (ib * 8 + u) * TPB);
                        }
                    }
                }
            }
        }
        __syncthreads();
        bool usefull = (T == NEGBIG) || (s_nw > WMAX);
        int total = usefull ? (HW / 4) : s_nw;

        // pass B: full 9-neighbor NMS on surviving quads
        for (int w = tid; w < total; w += TPB) {
            int i = usefull ? w : (int)s_work[w];
            float4 c4 = src4[i];
            int p = i << 2;
            int y = p >> 8;
            int x = p & 255;
            float L = (x > 0)   ? src[p - 1] : NEGBIG;
            float R = (x < 252) ? src[p + 4] : NEGBIG;
            float4 u4, d4; float uL, uR, dL, dR;
            if (y > 0) {
                u4 = src4[i - 64];
                uL = (x > 0)   ? src[p - 257] : NEGBIG;
                uR = (x < 252) ? src[p - 252] : NEGBIG;
            } else { u4 = make_float4(NEGBIG,NEGBIG,NEGBIG,NEGBIG); uL = uR = NEGBIG; }
            if (y < 255) {
                d4 = src4[i + 64];
                dL = (x > 0)   ? src[p + 255] : NEGBIG;
                dR = (x < 252) ? src[p + 260] : NEGBIG;
            } else { d4 = make_float4(NEGBIG,NEGBIG,NEGBIG,NEGBIG); dL = dR = NEGBIG; }

            float up01 = fmaxf(u4.x, u4.y), up12 = fmaxf(u4.y, u4.z), up23 = fmaxf(u4.z, u4.w);
            float wu0 = fmaxf(uL, up01), wu1 = fmaxf(up01, u4.z), wu2 = fmaxf(up12, u4.w), wu3 = fmaxf(up23, uR);
            float dp01 = fmaxf(d4.x, d4.y), dp12 = fmaxf(d4.y, d4.z), dp23 = fmaxf(d4.z, d4.w);
            float wd0 = fmaxf(dL, dp01), wd1 = fmaxf(dp01, d4.z), wd2 = fmaxf(dp12, d4.w), wd3 = fmaxf(dp23, dR);
            float hc0 = fmaxf(L, c4.y),    hc1 = fmaxf(c4.x, c4.z);
            float hc2 = fmaxf(c4.y, c4.w), hc3 = fmaxf(c4.z, R);
            float nms[4];
            nms[0] = fmaxf(wu0, fmaxf(hc0, wd0));
            nms[1] = fmaxf(wu1, fmaxf(hc1, wd1));
            nms[2] = fmaxf(wu2, fmaxf(hc2, wd2));
            nms[3] = fmaxf(wu3, fmaxf(hc3, wd3));
            float vs[4] = {c4.x, c4.y, c4.z, c4.w};
            bool ms[4];
            int npush = 0;
            #pragma unroll
            for (int s = 0; s < 4; s++) {
                bool m = (T == NEGBIG) || (vs[s] >= T);
                if (m) {
                    bool loc = vs[s] >= nms[s];
                    if (!loc && (nms[s] - vs[s]) < 1e-3f)
                        loc = (sigf(vs[s]) == sigf(nms[s]));  // sigmoid-rounding tie: ref keeps it
                    m = loc;
                }
                ms[s] = m;
                npush += m ? 1 : 0;
            }
            if (npush) {
                int pos = atomicAdd(&s_count, npush);
                #pragma unroll
                for (int s = 0; s < 4; s++) {
                    if (ms[s]) {
                        if (pos < MAXC) {
                            ckeys[pos] = __float_as_uint(sigf(vs[s]));
                            cinds[pos] = (unsigned short)(p + s);
                        }
                        pos++;
                    }
                }
            }
        }
        __syncthreads();
        count = min(s_count, MAXC);
        if ((s_count >= KK && s_count <= MAXC) || T == NEGBIG) break;
        T = NEGBIG;
        __syncthreads();
    }

    // ---- Phase 2: exact 100th-largest via 4-round MSB radix select ----
    unsigned prefix = 0;
    int n_higher = 0;
    for (int round = 0; round < 4; round++) {
        int shift = 24 - 8 * round;
        for (int h = tid; h < 8 * 256; h += TPB) ((int*)hist)[h] = 0;
        if (tid == 0) { s_bin = 0; s_nh = n_higher; }
        __syncthreads();
        int w8 = (tid >> 5) & 7;
        for (int c = tid; c < count; c += TPB) {
            unsigned key = ckeys[c];
            bool inr = (round == 0) || ((key >> (shift + 8)) == prefix);
            if (inr) atomicAdd(&hist[w8][(key >> shift) & 255], 1);
        }
        __syncthreads();
        int cbin = 0;
        if (tid < 256) {
            #pragma unroll
            for (int w = 0; w < 8; w++) cbin += hist[w][tid];
            int suf = cbin;
            #pragma unroll
            for (int off = 1; off < 32; off <<= 1) {
                int v = __shfl_down_sync(0xffffffffu, suf, off);
                if (lane + off < 32) suf += v;
            }
            int wid = tid >> 5;
            if (lane == 0) wtot[wid] = suf;
            __syncwarp();
            hist[1][tid] = suf - cbin;
        }
        __syncthreads();
        if (tid < 256) {
            int wid = tid >> 5;
            int hsum = 0;
            #pragma unroll
            for (int w = 0; w < 8; w++) if (w > wid) hsum += wtot[w];
            int sexcl = hist[1][tid] + hsum;
            int acc = n_higher + sexcl;
            if (acc < KK && acc + cbin >= KK) { s_bin = tid; s_nh = acc; }
        }
        __syncthreads();
        prefix = (prefix << 8) | (unsigned)s_bin;
        n_higher = s_nh;
        __syncthreads();
    }
    unsigned pivot = (count <= KK) ? 0u : prefix;

    // ---- Phase 3: collect >= pivot, exact rank (ties -> lower index first) ----
    if (tid == 0) s_m = 0;
    __syncthreads();
    for (int c = tid; c < count; c += TPB) {
        unsigned key = ckeys[c];
        if (key >= pivot) {
            int pos = atomicAdd(&s_m, 1);
            if (pos < MSEL) { s_selk[pos] = key; s_seli[pos] = (int)cinds[c]; }
        }
    }
    __syncthreads();
    int M = min(s_m, MSEL);

    if (is_writer) {
        if (tid < KK) { g_top_scores[b][tid] = 0.0f; g_top_inds[b][tid] = 0; }
        __syncthreads();
        for (int i = tid; i < M; i += TPB) {
            unsigned ki = s_selk[i]; int ii = s_seli[i];
            int rank = 0;
            for (int jq = 0; jq < M; jq++) {
                unsigned kj = s_selk[jq]; int ij = s_seli[jq];
                rank += (kj > ki || (kj == ki && ij < ii)) ? 1 : 0;
            }
            if (rank < KK) { g_top_scores[b][rank] = __uint_as_float(ki); g_top_inds[b][rank] = ii; }
        }
        __syncthreads();
        if (tid < KK) {
            int k = tid;
            int ind = g_top_inds[b][k];
            float score = g_top_scores[b][k];
            float x0 = (float)(ind & (WW - 1));
            float y0 = (float)(ind >> 8);
            const float* regb = reg + (long)b * 2 * HW;
            const float* whb  = wh  + (long)b * 2 * HW;
            float xs = x0 + regb[ind];
            float ys = y0 + regb[HW + ind];
            float w = whb[ind];
            float h = whb[HW + ind];
            float l  = xs - w * 0.5f;
            float t  = ys - h * 0.5f;
            float r  = xs + w * 0.5f;
            float bo = ys + h * 0.5f;
            g_bboxes[b][k][0] = l; g_bboxes[b][k][1] = t;
            g_bboxes[b][k][2] = r; g_bboxes[b][k][3] = bo;
            float* dr = out + o6 + (long)(b * KK + k) * 40;
            dr[0] = l; dr[1] = t; dr[2] = r; dr[3] = bo;
            dr[4] = score;
            dr[39] = 0.0f;
        }
        __syncthreads();
        if (tid == 0) {
            __threadfence();
            atomicExch(&g_ready[b], 1);
        }
        return;
    }

    // ======== reader: rank -> local hm-candidate arrays, spin, joints ========
    if (tid < KK) { shs[tid] = -1.0f; shx[tid] = -10000.0f; shy[tid] = -10000.0f; }
    __syncthreads();
    const float* hob = hpo + (long)b * 2 * HW;
    for (int i = tid; i < M; i += TPB) {
        unsigned ki = s_selk[i]; int ii = s_seli[i];
        int rank = 0;
        for (int jq = 0; jq < M; jq++) {
            unsigned kj = s_selk[jq]; int ij = s_seli[jq];
            rank += (kj > ki || (kj == ki && ij < ii)) ? 1 : 0;
        }
        if (rank < KK) {
            float s = __uint_as_float(ki);
            if (s > THRESH_F) {
                shs[rank] = s;
                shx[rank] = (float)(ii & (WW - 1)) + hob[ii];
                shy[rank] = (float)(ii >> 8) + hob[HW + ii];
            }
        }
    }
    __syncthreads();

    if (tid == 0) {
        while (((volatile int*)g_ready)[b] == 0) { __nanosleep(64); }
    }
    __syncthreads();
    __threadfence();

    if (tid < KK) {
        int k = tid;
        int ind = g_top_inds[b][k];
        float l  = g_bboxes[b][k][0];
        float tt = g_bboxes[b][k][1];
        float r  = g_bboxes[b][k][2];
        float bo = g_bboxes[b][k][3];
        const float* hpsb = hps + (long)b * (2 * JJ * HW);
        float kx = hpsb[(2 * j) * HW + ind] + (float)(ind & (WW - 1));
        float ky = hpsb[(2 * j + 1) * HW + ind] + (float)(ind >> 8);

        float md = 1e30f; int am = 0;
        #pragma unroll 4
        for (int m_ = 0; m_ < KK; m_++) {
            float dx = kx - shx[m_];
            float dy = ky - shy[m_];
            float d = sqrtf(dx * dx + dy * dy);
            if (d < md) { md = d; am = m_; }
        }
        float g   = shs[am];
        float hkx = shx[am];
        float hky = shy[am];
        bool bad = (hkx < l) || (hkx > r) || (hky < tt) || (hky > bo)
                || (g < THRESH_F) || (md > fmaxf(bo - tt, r - l) * 0.3f);
        float outx = bad ? kx : hkx;
        float outy = bad ? ky : hky;
        float* dr = out + o6 + (long)(b * KK + k) * 40;
        dr[5 + 2 * j] = outx;
        dr[6 + 2 * j] = outy;
    }
}

// ---------------- launch ----------------
extern "C" void kernel_launch(void* const* d_in, const int* in_sizes, int n_in,
                              void* d_out, int out_size) {
    const float* hm        = (const float*)d_in[0];
    const float* wh        = (const float*)d_in[1];
    const float* hps       = (const float*)d_in[2];
    const float* reg       = (const float*)d_in[3];
    const float* hm_hp     = (const float*)d_in[4];
    const float* hp_offset = (const float*)d_in[5];
    float* out = (float*)d_out;

    long o1 = in_sizes[0];
    long o2 = o1 + in_sizes[1];
    long o3 = o2 + in_sizes[2];
    long o4 = o3 + in_sizes[3];
    long o5 = o4 + in_sizes[4];
    long o6 = o5 + in_sizes[5];

    long e1 = o1 / 4, e2 = o2 / 4, e3 = o3 / 4, e4 = o4 / 4, e5 = o5 / 4, e6 = o6 / 4;

    reset_kernel<<<1, 32>>>();

    size_t dsmem = (size_t)MAXC * 6;  // uint keys + ushort inds
    cudaFuncSetAttribute(mega_kernel, cudaFuncAttributeMaxDynamicSharedMemorySize, (int)dsmem);
    mega_kernel<<<NCH + NSTREAM, TPB, dsmem>>>(hm, wh, hps, reg, hm_hp, hp_offset,
                                               out, e1, e2, e3, e4, e5, e6, o6);
}

// round 17
// speedup vs baseline: 1.2475x; 1.2475x over previous
#include <cuda_runtime.h>
#include <math.h>
#include <limits.h>

#define BB 8
#define HH 256
#define WW 256
#define KK 100
#define JJ 17
#define HW (HH*WW)
#define NCH (BB + BB*JJ)      // 144 topk blocks
#define NSTREAM 300
#define MAXC 12288
#define MSEL 512
#define WMAX 6144
#define TPB 512
#define TCNT 4                 // sample crossing target
#define THRESH_F 0.1f
#define NEGBIG (-1e30f)

// ---------------- scratch (device globals) ----------------
__device__ float g_top_scores[BB][KK];
__device__ int   g_top_inds[BB][KK];
__device__ float g_bboxes[BB][KK][4];
__device__ int   g_ready[BB];
__device__ int   g_ticket;
__device__ unsigned       g_ckeys[NCH][MAXC];   // candidate sigmoid bits (L2-resident)
__device__ unsigned short g_cinds[NCH][MAXC];   // candidate pixel idx

__device__ __forceinline__ float sigf(float x) { return 1.0f / (1.0f + expf(-x)); }
__device__ __forceinline__ unsigned fkey(float v) {
    unsigned b = __float_as_uint(v);
    return b ^ ((b & 0x80000000u) ? 0xFFFFFFFFu : 0x80000000u);
}

__global__ void reset_kernel() {
    if (threadIdx.x == 0) g_ticket = 0;
    if (threadIdx.x < BB) g_ready[threadIdx.x] = 0;
}

// ---------------- mega kernel ----------------
__global__ void __launch_bounds__(TPB, 3)
mega_kernel(const float* __restrict__ hm, const float* __restrict__ wh,
            const float* __restrict__ hps, const float* __restrict__ reg,
            const float* __restrict__ hmhp, const float* __restrict__ hpo,
            float* __restrict__ out,
            long e1, long e2, long e3, long e4, long e5, long e6, long o6) {
    const int tid = threadIdx.x;

    if (blockIdx.x >= NCH) {
        // ============ streaming: ticketed 128KB chunks, 4 batches of MLP-4 ============
        __shared__ int s_chunk;
        const int CH4 = 8192;   // float4 per chunk; divides every segment boundary exactly
        int nsc = (int)(e6 / CH4);
        float4* out4 = (float4*)out;
        while (true) {
            __syncthreads();
            if (tid == 0) s_chunk = atomicAdd(&g_ticket, 1);
            __syncthreads();
            int c = s_chunk;
            if (c >= nsc) return;
            long base = (long)c * CH4;
            const float4* src; bool sg = false;
            if (base < e1)      { src = (const float4*)hm   + base;        sg = true; }
            else if (base < e2) { src = (const float4*)wh   + (base - e1); }
            else if (base < e3) { src = (const float4*)hps  + (base - e2); }
            else if (base < e4) { src = (const float4*)reg  + (base - e3); }
            else if (base < e5) { src = (const float4*)hmhp + (base - e4); sg = true; }
            else                { src = (const float4*)hpo  + (base - e5); }
            #pragma unroll
            for (int h = 0; h < 4; h++) {
                float4 v[4];
                #pragma unroll
                for (int u = 0; u < 4; u++) v[u] = src[tid + (h * 4 + u) * TPB];
                if (sg) {
                    #pragma unroll
                    for (int u = 0; u < 4; u++) {
                        v[u].x = sigf(v[u].x); v[u].y = sigf(v[u].y);
                        v[u].z = sigf(v[u].z); v[u].w = sigf(v[u].w);
                    }
                }
                #pragma unroll
                for (int u = 0; u < 4; u++) out4[base + tid + (h * 4 + u) * TPB] = v[u];
            }
        }
    }

    // ============ topk block ============
    __shared__ int s_count;
    __shared__ int hist[8][256];
    __shared__ int wtot[8];
    __shared__ unsigned s_selk[MSEL];
    __shared__ int s_seli[MSEL];
    __shared__ int s_m;
    __shared__ int s_bin, s_nh;
    __shared__ int s_nw;
    __shared__ unsigned short s_work[WMAX];
    __shared__ float shx[KK], shy[KK], shs[KK];

    const int ch = blockIdx.x;
    const int lane = tid & 31;
    const bool is_writer = (ch < BB);
    const int e = ch - BB;
    const int b = is_writer ? ch : (e / JJ);
    const int j = is_writer ? 0 : (e % JJ);

    unsigned*       ckeys = g_ckeys[ch];
    unsigned short* cinds = g_cinds[ch];

    const float* src = is_writer ? (hm + (long)ch * HW)
                                 : (hmhp + (long)e * HW);
    const float4* src4 = (const float4*)src;

    // ---- Phase 0: sampled threshold (top-byte histogram of 512 strided pixels) ----
    if (tid == 0) s_bin = 0;
    for (int h = tid; h < 256; h += TPB) hist[0][h] = 0;
    __syncthreads();
    {
        unsigned sk = fkey(src[tid * 128]);
        atomicAdd(&hist[0][sk >> 24], 1);
    }
    __syncthreads();
    int cbin0 = 0;
    if (tid < 256) {
        cbin0 = hist[0][tid];
        int suf = cbin0;
        #pragma unroll
        for (int off = 1; off < 32; off <<= 1) {
            int v = __shfl_down_sync(0xffffffffu, suf, off);
            if (lane + off < 32) suf += v;
        }
        int wid = tid >> 5;
        if (lane == 0) wtot[wid] = suf;
        __syncwarp();
        hist[1][tid] = suf - cbin0;
    }
    __syncthreads();
    if (tid < 256) {
        int wid = tid >> 5;
        int hsum = 0;
        #pragma unroll
        for (int w = 0; w < 8; w++) if (w > wid) hsum += wtot[w];
        int sexcl = hist[1][tid] + hsum;
        if (sexcl < TCNT && sexcl + cbin0 >= TCNT) s_bin = tid;
    }
    __syncthreads();
    float T;
    {
        unsigned tk = (unsigned)s_bin << 24;
        T = (tk & 0x80000000u) ? __uint_as_float(tk & 0x7FFFFFFFu) : __uint_as_float(~tk);
    }
    __syncthreads();

    // ---- Phase 1: pass A (MLP-4 scan -> worklist) + pass B (NMS on worklist) ----
    int count;
    while (true) {
        if (tid == 0) { s_nw = 0; s_count = 0; }
        __syncthreads();

        if (T != NEGBIG) {
            #pragma unroll
            for (int ib = 0; ib < 8; ib++) {
                float4 v[4]; float cm[4];
                #pragma unroll
                for (int u = 0; u < 4; u++) v[u] = src4[tid + (ib * 4 + u) * TPB];
                #pragma unroll
                for (int u = 0; u < 4; u++)
                    cm[u] = fmaxf(fmaxf(v[u].x, v[u].y), fmaxf(v[u].z, v[u].w));
                #pragma unroll
                for (int u = 0; u < 4; u++) {
                    bool hit = cm[u] >= T;
                    unsigned ball = __ballot_sync(0xffffffffu, hit);
                    if (ball) {
                        int leader = __ffs(ball) - 1;
                        int basep = 0;
                        if (lane == leader) basep = atomicAdd(&s_nw, __popc(ball));
                        basep = __shfl_sync(0xffffffffu, basep, leader);
                        if (hit) {
                            int pos = basep + __popc(ball & ((1u << lane) - 1u));
                            if (pos < WMAX) s_work[pos] = (unsigned short)(tid + (ib * 4 + u) * TPB);
                        }
                    }
                }
            }
        }
        __syncthreads();
        bool usefull = (T == NEGBIG) || (s_nw > WMAX);
        int total = usefull ? (HW / 4) : s_nw;

        // pass B: full 9-neighbor NMS on surviving quads
        for (int w = tid; w < total; w += TPB) {
            int i = usefull ? w : (int)s_work[w];
            float4 c4 = src4[i];
            int p = i << 2;
            int y = p >> 8;
            int x = p & 255;
            float L = (x > 0)   ? src[p - 1] : NEGBIG;
            float R = (x < 252) ? src[p + 4] : NEGBIG;
            float4 u4, d4; float uL, uR, dL, dR;
            if (y > 0) {
                u4 = src4[i - 64];
                uL = (x > 0)   ? src[p - 257] : NEGBIG;
                uR = (x < 252) ? src[p - 252] : NEGBIG;
            } else { u4 = make_float4(NEGBIG,NEGBIG,NEGBIG,NEGBIG); uL = uR = NEGBIG; }
            if (y < 255) {
                d4 = src4[i + 64];
                dL = (x > 0)   ? src[p + 255] : NEGBIG;
                dR = (x < 252) ? src[p + 260] : NEGBIG;
            } else { d4 = make_float4(NEGBIG,NEGBIG,NEGBIG,NEGBIG); dL = dR = NEGBIG; }

            float up01 = fmaxf(u4.x, u4.y), up12 = fmaxf(u4.y, u4.z), up23 = fmaxf(u4.z, u4.w);
            float wu0 = fmaxf(uL, up01), wu1 = fmaxf(up01, u4.z), wu2 = fmaxf(up12, u4.w), wu3 = fmaxf(up23, uR);
            float dp01 = fmaxf(d4.x, d4.y), dp12 = fmaxf(d4.y, d4.z), dp23 = fmaxf(d4.z, d4.w);
            float wd0 = fmaxf(dL, dp01), wd1 = fmaxf(dp01, d4.z), wd2 = fmaxf(dp12, d4.w), wd3 = fmaxf(dp23, dR);
            float hc0 = fmaxf(L, c4.y),    hc1 = fmaxf(c4.x, c4.z);
            float hc2 = fmaxf(c4.y, c4.w), hc3 = fmaxf(c4.z, R);
            float nms[4];
            nms[0] = fmaxf(wu0, fmaxf(hc0, wd0));
            nms[1] = fmaxf(wu1, fmaxf(hc1, wd1));
            nms[2] = fmaxf(wu2, fmaxf(hc2, wd2));
            nms[3] = fmaxf(wu3, fmaxf(hc3, wd3));
            float vs[4] = {c4.x, c4.y, c4.z, c4.w};
            bool ms[4];
            int npush = 0;
            #pragma unroll
            for (int s = 0; s < 4; s++) {
                bool m = (T == NEGBIG) || (vs[s] >= T);
                if (m) {
                    bool loc = vs[s] >= nms[s];
                    if (!loc && (nms[s] - vs[s]) < 1e-3f)
                        loc = (sigf(vs[s]) == sigf(nms[s]));  // sigmoid-rounding tie: ref keeps it
                    m = loc;
                }
                ms[s] = m;
                npush += m ? 1 : 0;
            }
            if (npush) {
                int pos = atomicAdd(&s_count, npush);
                #pragma unroll
                for (int s = 0; s < 4; s++) {
                    if (ms[s]) {
                        if (pos < MAXC) {
                            ckeys[pos] = __float_as_uint(sigf(vs[s]));
                            cinds[pos] = (unsigned short)(p + s);
                        }
                        pos++;
                    }
                }
            }
        }
        __syncthreads();
        count = min(s_count, MAXC);
        if ((s_count >= KK && s_count <= MAXC) || T == NEGBIG) break;
        T = NEGBIG;
        __syncthreads();
    }

    // ---- Phase 2: exact 100th-largest via 4-round MSB radix select ----
    unsigned prefix = 0;
    int n_higher = 0;
    for (int round = 0; round < 4; round++) {
        int shift = 24 - 8 * round;
        for (int h = tid; h < 8 * 256; h += TPB) ((int*)hist)[h] = 0;
        if (tid == 0) { s_bin = 0; s_nh = n_higher; }
        __syncthreads();
        int w8 = (tid >> 5) & 7;
        for (int c = tid; c < count; c += TPB) {
            unsigned key = ckeys[c];
            bool inr = (round == 0) || ((key >> (shift + 8)) == prefix);
            if (inr) atomicAdd(&hist[w8][(key >> shift) & 255], 1);
        }
        __syncthreads();
        int cbin = 0;
        if (tid < 256) {
            #pragma unroll
            for (int w = 0; w < 8; w++) cbin += hist[w][tid];
            int suf = cbin;
            #pragma unroll
            for (int off = 1; off < 32; off <<= 1) {
                int v = __shfl_down_sync(0xffffffffu, suf, off);
                if (lane + off < 32) suf += v;
            }
            int wid = tid >> 5;
            if (lane == 0) wtot[wid] = suf;
            __syncwarp();
            hist[1][tid] = suf - cbin;
        }
        __syncthreads();
        if (tid < 256) {
            int wid = tid >> 5;
            int hsum = 0;
            #pragma unroll
            for (int w = 0; w < 8; w++) if (w > wid) hsum += wtot[w];
            int sexcl = hist[1][tid] + hsum;
            int acc = n_higher + sexcl;
            if (acc < KK && acc + cbin >= KK) { s_bin = tid; s_nh = acc; }
        }
        __syncthreads();
        prefix = (prefix << 8) | (unsigned)s_bin;
        n_higher = s_nh;
        __syncthreads();
    }
    unsigned pivot = (count <= KK) ? 0u : prefix;

    // ---- Phase 3: collect >= pivot, exact rank (ties -> lower index first) ----
    if (tid == 0) s_m = 0;
    __syncthreads();
    for (int c = tid; c < count; c += TPB) {
        unsigned key = ckeys[c];
        if (key >= pivot) {
            int pos = atomicAdd(&s_m, 1);
            if (pos < MSEL) { s_selk[pos] = key; s_seli[pos] = (int)cinds[c]; }
        }
    }
    __syncthreads();
    int M = min(s_m, MSEL);

    if (is_writer) {
        if (tid < KK) { g_top_scores[b][tid] = 0.0f; g_top_inds[b][tid] = 0; }
        __syncthreads();
        for (int i = tid; i < M; i += TPB) {
            unsigned ki = s_selk[i]; int ii = s_seli[i];
            int rank = 0;
            for (int jq = 0; jq < M; jq++) {
                unsigned kj = s_selk[jq]; int ij = s_seli[jq];
                rank += (kj > ki || (kj == ki && ij < ii)) ? 1 : 0;
            }
            if (rank < KK) { g_top_scores[b][rank] = __uint_as_float(ki); g_top_inds[b][rank] = ii; }
        }
        __syncthreads();
        if (tid < KK) {
            int k = tid;
            int ind = g_top_inds[b][k];
            float score = g_top_scores[b][k];
            float x0 = (float)(ind & (WW - 1));
            float y0 = (float)(ind >> 8);
            const float* regb = reg + (long)b * 2 * HW;
            const float* whb  = wh  + (long)b * 2 * HW;
            float xs = x0 + regb[ind];
            float ys = y0 + regb[HW + ind];
            float w = whb[ind];
            float h = whb[HW + ind];
            float l  = xs - w * 0.5f;
            float t  = ys - h * 0.5f;
            float r  = xs + w * 0.5f;
            float bo = ys + h * 0.5f;
            g_bboxes[b][k][0] = l; g_bboxes[b][k][1] = t;
            g_bboxes[b][k][2] = r; g_bboxes[b][k][3] = bo;
            float* dr = out + o6 + (long)(b * KK + k) * 40;
            dr[0] = l; dr[1] = t; dr[2] = r; dr[3] = bo;
            dr[4] = score;
            dr[39] = 0.0f;
        }
        __syncthreads();
        if (tid == 0) {
            __threadfence();
            atomicExch(&g_ready[b], 1);
        }
        return;
    }

    // ======== reader: rank -> local hm-candidate arrays, spin, joints ========
    if (tid < KK) { shs[tid] = -1.0f; shx[tid] = -10000.0f; shy[tid] = -10000.0f; }
    __syncthreads();
    const float* hob = hpo + (long)b * 2 * HW;
    for (int i = tid; i < M; i += TPB) {
        unsigned ki = s_selk[i]; int ii = s_seli[i];
        int rank = 0;
        for (int jq = 0; jq < M; jq++) {
            unsigned kj = s_selk[jq]; int ij = s_seli[jq];
            rank += (kj > ki || (kj == ki && ij < ii)) ? 1 : 0;
        }
        if (rank < KK) {
            float s = __uint_as_float(ki);
            if (s > THRESH_F) {
                shs[rank] = s;
                shx[rank] = (float)(ii & (WW - 1)) + hob[ii];
                shy[rank] = (float)(ii >> 8) + hob[HW + ii];
            }
        }
    }
    __syncthreads();

    if (tid == 0) {
        while (((volatile int*)g_ready)[b] == 0) { __nanosleep(64); }
    }
    __syncthreads();
    __threadfence();

    if (tid < KK) {
        int k = tid;
        int ind = g_top_inds[b][k];
        float l  = g_bboxes[b][k][0];
        float tt = g_bboxes[b][k][1];
        float r  = g_bboxes[b][k][2];
        float bo = g_bboxes[b][k][3];
        const float* hpsb = hps + (long)b * (2 * JJ * HW);
        float kx = hpsb[(2 * j) * HW + ind] + (float)(ind & (WW - 1));
        float ky = hpsb[(2 * j + 1) * HW + ind] + (float)(ind >> 8);

        float md = 1e30f; int am = 0;
        #pragma unroll 4
        for (int m_ = 0; m_ < KK; m_++) {
            float dx = kx - shx[m_];
            float dy = ky - shy[m_];
            float d = sqrtf(dx * dx + dy * dy);
            if (d < md) { md = d; am = m_; }
        }
        float g   = shs[am];
        float hkx = shx[am];
        float hky = shy[am];
        bool bad = (hkx < l) || (hkx > r) || (hky < tt) || (hky > bo)
                || (g < THRESH_F) || (md > fmaxf(bo - tt, r - l) * 0.3f);
        float outx = bad ? kx : hkx;
        float outy = bad ? ky : hky;
        float* dr = out + o6 + (long)(b * KK + k) * 40;
        dr[5 + 2 * j] = outx;
        dr[6 + 2 * j] = outy;
    }
}

// ---------------- launch ----------------
extern "C" void kernel_launch(void* const* d_in, const int* in_sizes, int n_in,
                              void* d_out, int out_size) {
    const float* hm        = (const float*)d_in[0];
    const float* wh        = (const float*)d_in[1];
    const float* hps       = (const float*)d_in[2];
    const float* reg       = (const float*)d_in[3];
    const float* hm_hp     = (const float*)d_in[4];
    const float* hp_offset = (const float*)d_in[5];
    float* out = (float*)d_out;

    long o1 = in_sizes[0];
    long o2 = o1 + in_sizes[1];
    long o3 = o2 + in_sizes[2];
    long o4 = o3 + in_sizes[3];
    long o5 = o4 + in_sizes[4];
    long o6 = o5 + in_sizes[5];

    long e1 = o1 / 4, e2 = o2 / 4, e3 = o3 / 4, e4 = o4 / 4, e5 = o5 / 4, e6 = o6 / 4;

    reset_kernel<<<1, 32>>>();

    mega_kernel<<<NCH + NSTREAM, TPB>>>(hm, wh, hps, reg, hm_hp, hp_offset,
                                        out, e1, e2, e3, e4, e5, e6, o6);
}